// round 9
// baseline (speedup 1.0000x reference)
#include <cuda_runtime.h>
#include <cuda_fp16.h>
#include <cstdint>

#define NMAX 50000
#define NEMAX 1000000

// ---------------- scratch ----------------
__device__ __align__(16) __half g_P16a[(size_t)NMAX * 128];
__device__ __align__(16) __half g_P16b[(size_t)NMAX * 128];
__device__ __align__(16) float  g_P40 [(size_t)NMAX * 40 + 8];
__device__ __align__(16) int    g_outdeg[NMAX + 8];
__device__ __align__(16) int    g_indeg [NMAX + 8];
__device__ int g_esrc[NEMAX];
__device__ int g_rowstart[NMAX + 8];
__device__ int g_cursor[NMAX + 8];

// ---------------- packed f32x2 helpers ----------------
__device__ __forceinline__ uint32_t smem_u32(const void* p) {
    uint32_t a;
    asm("{ .reg .u64 t; cvta.to.shared.u64 t, %1; cvt.u32.u64 %0, t; }" : "=r"(a) : "l"(p));
    return a;
}
__device__ __forceinline__ unsigned long long lds_b64(uint32_t a) {
    unsigned long long v;
    asm volatile("ld.shared.b64 %0, [%1];" : "=l"(v) : "r"(a));
    return v;
}
__device__ __forceinline__ uint32_t lds_b32(uint32_t a) {
    uint32_t v;
    asm volatile("ld.shared.b32 %0, [%1];" : "=r"(v) : "r"(a));
    return v;
}
__device__ __forceinline__ unsigned long long dup2(uint32_t x) {
    unsigned long long v;
    asm("mov.b64 %0, {%1, %1};" : "=l"(v) : "r"(x));
    return v;
}
__device__ __forceinline__ void fma2(unsigned long long& d, unsigned long long a, unsigned long long b) {
    asm("fma.rn.f32x2 %0, %1, %2, %0;" : "+l"(d) : "l"(a), "l"(b));
}

// ---------------- prologue kernels ----------------
__global__ void k_deg_both(const int* __restrict__ src, const int* __restrict__ dst, int nE) {
    int i = blockIdx.x * blockDim.x + threadIdx.x;
    if (i < nE) {
        atomicAdd(&g_outdeg[src[i]], 1);
        atomicAdd(&g_indeg[dst[i]], 1);
    }
}

// single-block scan over indeg -> rowstart/cursor (1024 threads)
__global__ void __launch_bounds__(1024)
k_scan_all(int n) {
    __shared__ int part[1024];
    int tid = threadIdx.x;
    int chunk = (n + 1023) >> 10;
    int s = tid * chunk;
    int e = min(s + chunk, n);
    int sum = 0;
    for (int i = s; i < e; ++i) sum += g_indeg[i];
    part[tid] = sum;
    __syncthreads();
    for (int off = 1; off < 1024; off <<= 1) {
        int t = 0;
        if (tid >= off) t = part[tid - off];
        __syncthreads();
        if (tid >= off) part[tid] += t;
        __syncthreads();
    }
    int run = part[tid] - sum;   // exclusive prefix
    for (int i = s; i < e; ++i) {
        int d = g_indeg[i];
        g_rowstart[i] = run;
        g_cursor[i]   = run;
        run += d;
    }
    if (tid == 1023) g_rowstart[n] = run;
}

__global__ void k_scatter(const int* __restrict__ src, const int* __restrict__ dst, int nE) {
    int i = blockIdx.x * blockDim.x + threadIdx.x;
    if (i < nE) {
        int d = dst[i];
        int pos = atomicAdd(&g_cursor[d], 1);
        g_esrc[pos] = src[i];
    }
}

// ---------------- shared GEMM inner (FFMA2), Xs already staged ----------------
// Xs: [128][132] fp32 at smem offset 0. Ws: [64][128] staged per K-half at WS_OFF.
#define WS_OFF (128 * 132 * 4)

__device__ __forceinline__ void gemm128_core(
    const float* __restrict__ W, float* sm, uint32_t smem_base,
    int tid, unsigned long long acc[8][4])
{
    const int tx = tid & 15;
    const int ty = tid >> 4;
    float* Ws = sm + 128 * 132;
    const uint32_t xrow0 = smem_base + (uint32_t)(ty * 8 * 132) * 4;
    const uint32_t wbase = smem_base + WS_OFF + (uint32_t)tx * 16;

    for (int half = 0; half < 2; ++half) {
        __syncthreads();
        for (int q = tid; q < 64 * 32; q += 256)
            ((float4*)Ws)[q] = ((const float4*)W)[half * 2048 + q];
        __syncthreads();

        const uint32_t xh = xrow0 + (uint32_t)(half * 64) * 4;
#pragma unroll 2
        for (int kk = 0; kk < 64; ++kk) {
            uint32_t wb = wbase + (uint32_t)kk * 512;
            unsigned long long b0 = lds_b64(wb);
            unsigned long long b1 = lds_b64(wb + 8);
            unsigned long long b2 = lds_b64(wb + 256);
            unsigned long long b3 = lds_b64(wb + 264);
#pragma unroll
            for (int i = 0; i < 8; ++i) {
                unsigned long long ap = dup2(lds_b32(xh + (uint32_t)(i * 132 + kk) * 4));
                fma2(acc[i][0], ap, b0);
                fma2(acc[i][1], ap, b1);
                fma2(acc[i][2], ap, b2);
                fma2(acc[i][3], ap, b3);
            }
        }
    }
}

__device__ __forceinline__ void store_p16(
    __half* __restrict__ P, int r0, int n, int tid, unsigned long long acc[8][4])
{
    const int tx = tid & 15;
    const int ty = tid >> 4;
#pragma unroll
    for (int i = 0; i < 8; ++i) {
        int gr = r0 + ty * 8 + i;
        if (gr >= n) continue;
        __half* prow = P + (size_t)gr * 128;
        float2 p0 = *(float2*)&acc[i][0];
        float2 p1 = *(float2*)&acc[i][1];
        float2 p2 = *(float2*)&acc[i][2];
        float2 p3 = *(float2*)&acc[i][3];
        __half2 h0 = __floats2half2_rn(p0.x, p0.y);
        __half2 h1 = __floats2half2_rn(p1.x, p1.y);
        __half2 h2 = __floats2half2_rn(p2.x, p2.y);
        __half2 h3 = __floats2half2_rn(p3.x, p3.y);
        uint2 w0; w0.x = *(uint32_t*)&h0; w0.y = *(uint32_t*)&h1;
        uint2 w1; w1.x = *(uint32_t*)&h2; w1.y = *(uint32_t*)&h3;
        *(uint2*)(prow + 4 * tx)      = w0;
        *(uint2*)(prow + 64 + 4 * tx) = w1;
    }
}

// ---------------- GEMM layer 1: X*onorm @ W1 -> P16a ----------------
__global__ void __launch_bounds__(256)
k_gemm1(const float* __restrict__ X, const float* __restrict__ W,
        __half* __restrict__ P, int n) {
    extern __shared__ float sm[];
    const uint32_t smem_base = smem_u32(sm);
    const int tid = threadIdx.x;
    const int r0  = blockIdx.x * 128;

    for (int q = tid; q < 128 * 32; q += 256) {
        int r = q >> 5, c4 = q & 31;
        int gr = r0 + r;
        float4 v = make_float4(0.f, 0.f, 0.f, 0.f);
        if (gr < n) {
            v = ((const float4*)(X + (size_t)gr * 128))[c4];
            float s = rsqrtf(fmaxf((float)g_outdeg[gr], 1.f));
            v.x *= s; v.y *= s; v.z *= s; v.w *= s;
        }
        *((float4*)(sm + r * 132 + c4 * 4)) = v;
    }

    unsigned long long acc[8][4];
#pragma unroll
    for (int i = 0; i < 8; ++i)
#pragma unroll
        for (int j = 0; j < 4; ++j) acc[i][j] = 0ull;

    gemm128_core(W, sm, smem_base, tid, acc);
    store_p16(P, r0, n, tid, acc);
}

// ---------------- fused phase-1: CSR agg (fp16 src) -> Xs smem ----------------
// Warp per node (8 warps cover 128 rows); epilogue = relu(acc*inorm + b)*onorm.
__device__ __forceinline__ void agg_to_smem(
    const uint4* __restrict__ Psrc, const float* __restrict__ bias,
    float* sm, int r0, int n, int tid)
{
    const int wid  = tid >> 5;
    const int lane = tid & 31;
    const int sub  = lane & 15;
    const int grp  = lane >> 4;

    float4 bb0 = ((const float4*)bias)[sub * 2];
    float4 bb1 = ((const float4*)bias)[sub * 2 + 1];

    for (int t = wid; t < 128; t += 8) {
        int node = r0 + t;
        float acc[8];
#pragma unroll
        for (int j = 0; j < 8; ++j) acc[j] = 0.f;

        if (node < n) {
            int beg = g_rowstart[node];
            int end = g_rowstart[node + 1];
            for (int base = beg; base < end; base += 32) {
                int cnt = min(32, end - base);
                int myidx = (lane < cnt) ? g_esrc[base + lane] : 0;
                int j = 0;
                for (; j + 4 <= cnt; j += 4) {
                    int sA = __shfl_sync(0xffffffffu, myidx, j + grp);
                    int sB = __shfl_sync(0xffffffffu, myidx, j + 2 + grp);
                    uint4 vA = Psrc[(size_t)sA * 16 + sub];
                    uint4 vB = Psrc[(size_t)sB * 16 + sub];
#pragma unroll
                    for (int q = 0; q < 4; ++q) {
                        uint32_t uA = (&vA.x)[q];
                        uint32_t uB = (&vB.x)[q];
                        float2 fA = __half22float2(*(__half2*)&uA);
                        float2 fB = __half22float2(*(__half2*)&uB);
                        acc[2 * q]     += fA.x + fB.x;
                        acc[2 * q + 1] += fA.y + fB.y;
                    }
                }
                for (; j + 2 <= cnt; j += 2) {
                    int s = __shfl_sync(0xffffffffu, myidx, j + grp);
                    uint4 v = Psrc[(size_t)s * 16 + sub];
#pragma unroll
                    for (int q = 0; q < 4; ++q) {
                        uint32_t u = (&v.x)[q];
                        float2 f = __half22float2(*(__half2*)&u);
                        acc[2 * q]     += f.x;
                        acc[2 * q + 1] += f.y;
                    }
                }
                if (j < cnt) {
                    int s = __shfl_sync(0xffffffffu, myidx, j);
                    if (grp == 0) {
                        uint4 v = Psrc[(size_t)s * 16 + sub];
#pragma unroll
                        for (int q = 0; q < 4; ++q) {
                            uint32_t u = (&v.x)[q];
                            float2 f = __half22float2(*(__half2*)&u);
                            acc[2 * q]     += f.x;
                            acc[2 * q + 1] += f.y;
                        }
                    }
                }
            }
        }

#pragma unroll
        for (int q = 0; q < 8; ++q)
            acc[q] += __shfl_xor_sync(0xffffffffu, acc[q], 16);

        if (grp == 0) {
            float4 r0v = make_float4(0.f, 0.f, 0.f, 0.f);
            float4 r1v = make_float4(0.f, 0.f, 0.f, 0.f);
            if (node < n) {
                float in = rsqrtf(fmaxf((float)g_indeg[node], 1.f));
                float on = rsqrtf(fmaxf((float)g_outdeg[node], 1.f));
                r0v.x = fmaxf(fmaf(acc[0], in, bb0.x), 0.f) * on;
                r0v.y = fmaxf(fmaf(acc[1], in, bb0.y), 0.f) * on;
                r0v.z = fmaxf(fmaf(acc[2], in, bb0.z), 0.f) * on;
                r0v.w = fmaxf(fmaf(acc[3], in, bb0.w), 0.f) * on;
                r1v.x = fmaxf(fmaf(acc[4], in, bb1.x), 0.f) * on;
                r1v.y = fmaxf(fmaf(acc[5], in, bb1.y), 0.f) * on;
                r1v.z = fmaxf(fmaf(acc[6], in, bb1.z), 0.f) * on;
                r1v.w = fmaxf(fmaf(acc[7], in, bb1.w), 0.f) * on;
            }
            *(float4*)(sm + t * 132 + sub * 8)     = r0v;
            *(float4*)(sm + t * 132 + sub * 8 + 4) = r1v;
        }
    }
}

// ---------------- fusedA: agg(P16a, b1) -> GEMM W2 -> P16b ----------------
__global__ void __launch_bounds__(256)
k_fusedA(const float* __restrict__ b1, const float* __restrict__ W2,
         __half* __restrict__ Pout, int n) {
    extern __shared__ float sm[];
    const uint32_t smem_base = smem_u32(sm);
    const int tid = threadIdx.x;
    const int r0  = blockIdx.x * 128;

    agg_to_smem((const uint4*)g_P16a, b1, sm, r0, n, tid);

    unsigned long long acc[8][4];
#pragma unroll
    for (int i = 0; i < 8; ++i)
#pragma unroll
        for (int j = 0; j < 4; ++j) acc[i][j] = 0ull;

    gemm128_core(W2, sm, smem_base, tid, acc);   // first __syncthreads orders Xs
    store_p16(Pout, r0, n, tid, acc);
}

// ---------------- fusedB: agg(P16b, b2) -> GEMM W3 (128->40) -> P40 ----------------
__global__ void __launch_bounds__(256)
k_fusedB(const float* __restrict__ b2, const float* __restrict__ W3,
         float* __restrict__ Pout, int n) {
    extern __shared__ float sm[];
    const int tid = threadIdx.x;
    const int r0  = blockIdx.x * 128;
    float* Ws = sm + 128 * 132;   // [128][64] padded

    agg_to_smem((const uint4*)g_P16b, b2, sm, r0, n, tid);

    // stage W3 padded to 64 cols
    __syncthreads();
    for (int q = tid; q < 128 * 64; q += 256) {
        int k = q >> 6, c = q & 63;
        Ws[q] = (c < 40) ? W3[k * 40 + c] : 0.f;
    }
    __syncthreads();

    const int tx = tid & 15;   // col group (4 cols)
    const int ty = tid >> 4;   // row group (8 rows)
    float acc[8][4];
#pragma unroll
    for (int i = 0; i < 8; ++i)
#pragma unroll
        for (int j = 0; j < 4; ++j) acc[i][j] = 0.f;

    const float* xb = sm + ty * 8 * 132;
    const float4* wc = ((const float4*)Ws) + tx;
#pragma unroll 4
    for (int k = 0; k < 128; ++k) {
        float4 b = wc[k * 16];
#pragma unroll
        for (int i = 0; i < 8; ++i) {
            float a = xb[i * 132 + k];
            acc[i][0] = fmaf(a, b.x, acc[i][0]);
            acc[i][1] = fmaf(a, b.y, acc[i][1]);
            acc[i][2] = fmaf(a, b.z, acc[i][2]);
            acc[i][3] = fmaf(a, b.w, acc[i][3]);
        }
    }

    if (tx < 10) {
#pragma unroll
        for (int i = 0; i < 8; ++i) {
            int gr = r0 + ty * 8 + i;
            if (gr >= n) continue;
            *(float4*)(Pout + (size_t)gr * 40 + 4 * tx) =
                make_float4(acc[i][0], acc[i][1], acc[i][2], acc[i][3]);
        }
    }
}

// ---------------- final aggregation over fp32 P40 (40 dims) ----------------
__global__ void __launch_bounds__(256)
k_agg40(const float* __restrict__ b, float* __restrict__ out, int n) {
    int t = blockIdx.x * blockDim.x + threadIdx.x;
    if (t >= n * 10) return;
    int node = t / 10;
    int g    = t - node * 10;

    int beg = g_rowstart[node];
    int end = g_rowstart[node + 1];

    float4 acc = make_float4(0.f, 0.f, 0.f, 0.f);
    const float4* P4 = (const float4*)g_P40;
    int e = beg;
    for (; e + 2 <= end; e += 2) {
        int s0 = g_esrc[e];
        int s1 = g_esrc[e + 1];
        float4 v0 = P4[(size_t)s0 * 10 + g];
        float4 v1 = P4[(size_t)s1 * 10 + g];
        acc.x += v0.x; acc.y += v0.y; acc.z += v0.z; acc.w += v0.w;
        acc.x += v1.x; acc.y += v1.y; acc.z += v1.z; acc.w += v1.w;
    }
    if (e < end) {
        int s = g_esrc[e];
        float4 v = P4[(size_t)s * 10 + g];
        acc.x += v.x; acc.y += v.y; acc.z += v.z; acc.w += v.w;
    }

    float sc = rsqrtf(fmaxf((float)g_indeg[node], 1.f));
    float4 bb = ((const float4*)b)[g];
    float4 r;
    r.x = fmaf(acc.x, sc, bb.x);
    r.y = fmaf(acc.y, sc, bb.y);
    r.z = fmaf(acc.z, sc, bb.z);
    r.w = fmaf(acc.w, sc, bb.w);
    ((float4*)(out + (size_t)node * 40))[g] = r;
}

// ---------------- launch ----------------
extern "C" void kernel_launch(void* const* d_in, const int* in_sizes, int n_in,
                              void* d_out, int out_size) {
    const float* feat = (const float*)d_in[0];
    const float* W1   = (const float*)d_in[1];
    const float* b1   = (const float*)d_in[2];
    const float* W2   = (const float*)d_in[3];
    const float* b2   = (const float*)d_in[4];
    const float* W3   = (const float*)d_in[5];
    const float* b3   = (const float*)d_in[6];
    const int*   src  = (const int*)d_in[7];
    const int*   dst  = (const int*)d_in[8];

    const int N  = in_sizes[0] / 128;
    const int nE = in_sizes[7];
    float* out = (float*)d_out;

    __half *P16a = nullptr, *P16b = nullptr;
    float* P40 = nullptr;
    void *odeg = nullptr, *ideg = nullptr;
    cudaGetSymbolAddress((void**)&P16a, g_P16a);
    cudaGetSymbolAddress((void**)&P16b, g_P16b);
    cudaGetSymbolAddress((void**)&P40, g_P40);
    cudaGetSymbolAddress(&odeg, g_outdeg);
    cudaGetSymbolAddress(&ideg, g_indeg);

    const int SMEM = (128 * 132 + 64 * 128) * 4;   // 100352 B (Xs + W staging)
    cudaFuncSetAttribute(k_gemm1,  cudaFuncAttributeMaxDynamicSharedMemorySize, SMEM);
    cudaFuncSetAttribute(k_fusedA, cudaFuncAttributeMaxDynamicSharedMemorySize, SMEM);
    cudaFuncSetAttribute(k_fusedB, cudaFuncAttributeMaxDynamicSharedMemorySize, SMEM);

    const int T = 256;
    const int gemmBlocks = (N + 127) / 128;
    const int eBlocks    = (nE + T - 1) / T;

    cudaStream_t s1;
    cudaStreamCreateWithFlags(&s1, cudaStreamNonBlocking);
    cudaEvent_t e1, e2;
    cudaEventCreateWithFlags(&e1, cudaEventDisableTiming);
    cudaEventCreateWithFlags(&e2, cudaEventDisableTiming);

    // prologue: both degree histograms in one kernel
    cudaMemsetAsync(odeg, 0, (size_t)N * 4, 0);
    cudaMemsetAsync(ideg, 0, (size_t)N * 4, 0);
    k_deg_both<<<eBlocks, T>>>(src, dst, nE);

    // fork: CSR build on s1, GEMM1 on main
    cudaEventRecord(e1, 0);
    cudaStreamWaitEvent(s1, e1, 0);
    k_scan_all<<<1, 1024, 0, s1>>>(N);
    k_scatter<<<eBlocks, T, 0, s1>>>(src, dst, nE);
    cudaEventRecord(e2, s1);

    k_gemm1<<<gemmBlocks, T, SMEM>>>(feat, W1, P16a, N);

    // join
    cudaStreamWaitEvent(0, e2, 0);

    // fused layers
    k_fusedA<<<gemmBlocks, T, SMEM>>>(b1, W2, P16b, N);
    k_fusedB<<<gemmBlocks, T, SMEM>>>(b2, W3, P40, N);
    k_agg40<<<(N * 10 + T - 1) / T, T>>>(b3, out, N);

    cudaStreamCaptureStatus cap = cudaStreamCaptureStatusNone;
    cudaStreamIsCapturing(s1, &cap);
    if (cap == cudaStreamCaptureStatusNone) {
        cudaEventDestroy(e1);
        cudaEventDestroy(e2);
        cudaStreamDestroy(s1);
    }
}

// round 10
// speedup vs baseline: 1.2608x; 1.2608x over previous
#include <cuda_runtime.h>
#include <cuda_fp16.h>
#include <cstdint>

#define NMAX 50000
#define NEMAX 1000000

// ---------------- scratch ----------------
__device__ __align__(16) __half g_P16[(size_t)NMAX * 128];
__device__ __align__(16) float  g_P  [(size_t)NMAX * 40 + 8];
__device__ __align__(16) float  g_H  [(size_t)NMAX * 128];
__device__ __align__(16) int    g_outdeg[NMAX + 8];
__device__ __align__(16) int    g_indeg [NMAX + 8];
__device__ int g_esrc[NEMAX];
__device__ int g_rowstart[NMAX + 8];
__device__ int g_cursor[NMAX + 8];

// ---------------- packed f32x2 helpers ----------------
__device__ __forceinline__ uint32_t smem_u32(const void* p) {
    uint32_t a;
    asm("{ .reg .u64 t; cvta.to.shared.u64 t, %1; cvt.u32.u64 %0, t; }" : "=r"(a) : "l"(p));
    return a;
}
__device__ __forceinline__ unsigned long long lds_b64(uint32_t a) {
    unsigned long long v;
    asm volatile("ld.shared.b64 %0, [%1];" : "=l"(v) : "r"(a));
    return v;
}
__device__ __forceinline__ void lds_2x32(uint32_t a, uint32_t& r0, uint32_t& r1) {
    asm volatile("ld.shared.v2.b32 {%0, %1}, [%2];" : "=r"(r0), "=r"(r1) : "r"(a));
}
__device__ __forceinline__ unsigned long long dup2(uint32_t x) {
    unsigned long long v;
    asm("mov.b64 %0, {%1, %1};" : "=l"(v) : "r"(x));
    return v;
}
__device__ __forceinline__ void fma2(unsigned long long& d, unsigned long long a, unsigned long long b) {
    asm("fma.rn.f32x2 %0, %1, %2, %0;" : "+l"(d) : "l"(a), "l"(b));
}

// ---------------- prologue ----------------
__global__ void k_deg_both(const int* __restrict__ src, const int* __restrict__ dst, int nE) {
    int i = blockIdx.x * blockDim.x + threadIdx.x;
    if (i < nE) {
        atomicAdd(&g_outdeg[src[i]], 1);
        atomicAdd(&g_indeg[dst[i]], 1);
    }
}

__global__ void __launch_bounds__(1024)
k_scan_all(int n) {
    __shared__ int part[1024];
    int tid = threadIdx.x;
    int chunk = (n + 1023) >> 10;
    int s = tid * chunk;
    int e = min(s + chunk, n);
    int sum = 0;
    for (int i = s; i < e; ++i) sum += g_indeg[i];
    part[tid] = sum;
    __syncthreads();
    for (int off = 1; off < 1024; off <<= 1) {
        int t = 0;
        if (tid >= off) t = part[tid - off];
        __syncthreads();
        if (tid >= off) part[tid] += t;
        __syncthreads();
    }
    int run = part[tid] - sum;
    for (int i = s; i < e; ++i) {
        int d = g_indeg[i];
        g_rowstart[i] = run;
        g_cursor[i]   = run;
        run += d;
    }
    if (tid == 1023) g_rowstart[n] = run;
}

__global__ void k_scatter(const int* __restrict__ src, const int* __restrict__ dst, int nE) {
    int i = blockIdx.x * blockDim.x + threadIdx.x;
    if (i < nE) {
        int d = dst[i];
        int pos = atomicAdd(&g_cursor[d], 1);
        g_esrc[pos] = src[i];
    }
}

// ---------------- GEMM 64x128 tile, FFMA2, fp16 output (3 CTAs/SM) ----------
// 256 threads: ty = tid>>4 (16 row-groups x 4 rows), tx = tid&15 (cols 4tx and 64+4tx).
__global__ void __launch_bounds__(256)
k_gemm64_h(const float* __restrict__ X, const float* __restrict__ W,
           __half* __restrict__ P, int n) {
    extern __shared__ float sm[];
    const uint32_t smem_base = smem_u32(sm);
    const uint32_t WS_OFF = 64 * 132 * 4;      // Xs: [64][132]

    const int tid = threadIdx.x;
    const int r0  = blockIdx.x * 64;
    const int tx  = tid & 15;
    const int ty  = tid >> 4;

    // stage X tile (64 rows) with onorm fused
    for (int q = tid; q < 64 * 32; q += 256) {
        int r = q >> 5, c4 = q & 31;
        int gr = r0 + r;
        float4 v = make_float4(0.f, 0.f, 0.f, 0.f);
        if (gr < n) {
            v = ((const float4*)(X + (size_t)gr * 128))[c4];
            float s = rsqrtf(fmaxf((float)g_outdeg[gr], 1.f));
            v.x *= s; v.y *= s; v.z *= s; v.w *= s;
        }
        *((float4*)(sm + r * 132 + c4 * 4)) = v;
    }

    unsigned long long acc[4][4];
#pragma unroll
    for (int i = 0; i < 4; ++i)
#pragma unroll
        for (int j = 0; j < 4; ++j) acc[i][j] = 0ull;

    const uint32_t xrow0 = smem_base + (uint32_t)(ty * 4 * 132) * 4;
    const uint32_t wbase = smem_base + WS_OFF + (uint32_t)tx * 16;

    for (int half = 0; half < 2; ++half) {
        __syncthreads();
        for (int q = tid; q < 64 * 32; q += 256)
            ((float4*)(sm + 64 * 132))[q] = ((const float4*)W)[half * 2048 + q];
        __syncthreads();

        const uint32_t xh = xrow0 + (uint32_t)(half * 64) * 4;
#pragma unroll 2
        for (int kk = 0; kk < 64; kk += 2) {
            // a pairs for 4 rows, two k's each
            uint32_t a0k0, a0k1, a1k0, a1k1, a2k0, a2k1, a3k0, a3k1;
            lds_2x32(xh + (uint32_t)(0 * 132 + kk) * 4, a0k0, a0k1);
            lds_2x32(xh + (uint32_t)(1 * 132 + kk) * 4, a1k0, a1k1);
            lds_2x32(xh + (uint32_t)(2 * 132 + kk) * 4, a2k0, a2k1);
            lds_2x32(xh + (uint32_t)(3 * 132 + kk) * 4, a3k0, a3k1);

            uint32_t wb0 = wbase + (uint32_t)kk * 512;
            uint32_t wb1 = wb0 + 512;
            unsigned long long b00 = lds_b64(wb0);
            unsigned long long b01 = lds_b64(wb0 + 256);
            unsigned long long b10 = lds_b64(wb1);
            unsigned long long b11 = lds_b64(wb1 + 256);
            unsigned long long c00 = lds_b64(wb0 + 8);
            unsigned long long c01 = lds_b64(wb0 + 264);
            unsigned long long c10 = lds_b64(wb1 + 8);
            unsigned long long c11 = lds_b64(wb1 + 264);

            unsigned long long p0 = dup2(a0k0), q0 = dup2(a0k1);
            unsigned long long p1 = dup2(a1k0), q1 = dup2(a1k1);
            unsigned long long p2 = dup2(a2k0), q2 = dup2(a2k1);
            unsigned long long p3 = dup2(a3k0), q3 = dup2(a3k1);

            fma2(acc[0][0], p0, b00); fma2(acc[0][1], p0, c00);
            fma2(acc[0][2], p0, b01); fma2(acc[0][3], p0, c01);
            fma2(acc[1][0], p1, b00); fma2(acc[1][1], p1, c00);
            fma2(acc[1][2], p1, b01); fma2(acc[1][3], p1, c01);
            fma2(acc[2][0], p2, b00); fma2(acc[2][1], p2, c00);
            fma2(acc[2][2], p2, b01); fma2(acc[2][3], p2, c01);
            fma2(acc[3][0], p3, b00); fma2(acc[3][1], p3, c00);
            fma2(acc[3][2], p3, b01); fma2(acc[3][3], p3, c01);

            fma2(acc[0][0], q0, b10); fma2(acc[0][1], q0, c10);
            fma2(acc[0][2], q0, b11); fma2(acc[0][3], q0, c11);
            fma2(acc[1][0], q1, b10); fma2(acc[1][1], q1, c10);
            fma2(acc[1][2], q1, b11); fma2(acc[1][3], q1, c11);
            fma2(acc[2][0], q2, b10); fma2(acc[2][1], q2, c10);
            fma2(acc[2][2], q2, b11); fma2(acc[2][3], q2, c11);
            fma2(acc[3][0], q3, b10); fma2(acc[3][1], q3, c10);
            fma2(acc[3][2], q3, b11); fma2(acc[3][3], q3, c11);
        }
    }

#pragma unroll
    for (int i = 0; i < 4; ++i) {
        int gr = r0 + ty * 4 + i;
        if (gr >= n) continue;
        __half* prow = P + (size_t)gr * 128;
        float2 p0 = *(float2*)&acc[i][0];   // cols 4tx, 4tx+1
        float2 p1 = *(float2*)&acc[i][1];   // cols 4tx+2, 4tx+3
        float2 p2 = *(float2*)&acc[i][2];   // cols 64+4tx..
        float2 p3 = *(float2*)&acc[i][3];
        __half2 h0 = __floats2half2_rn(p0.x, p0.y);
        __half2 h1 = __floats2half2_rn(p1.x, p1.y);
        __half2 h2 = __floats2half2_rn(p2.x, p2.y);
        __half2 h3 = __floats2half2_rn(p3.x, p3.y);
        uint2 w0; w0.x = *(uint32_t*)&h0; w0.y = *(uint32_t*)&h1;
        uint2 w1; w1.x = *(uint32_t*)&h2; w1.y = *(uint32_t*)&h3;
        *(uint2*)(prow + 4 * tx)      = w0;
        *(uint2*)(prow + 64 + 4 * tx) = w1;
    }
}

// ---------------- GEMM layer 3 (128 -> 40), fp32 ----------------
template<int COLS, int NCOUT>
__global__ void __launch_bounds__(256)
k_gemm(const float* __restrict__ X, const float* __restrict__ W,
       float* __restrict__ P, int n) {
    extern __shared__ float sm[];
    float* Ws = sm;
    float* Xs = sm + 128 * COLS;

    const int tid = threadIdx.x;
    const int r0  = blockIdx.x * 64;

    for (int q = tid; q < 128 * COLS; q += 256) {
        int k = q / COLS, c = q % COLS;
        Ws[q] = (c < NCOUT) ? W[k * NCOUT + c] : 0.f;
    }
    for (int q = tid; q < 64 * 32; q += 256) {
        int r = q >> 5, c4 = q & 31;
        int gr = r0 + r;
        float4 v = make_float4(0.f, 0.f, 0.f, 0.f);
        if (gr < n) {
            v = ((const float4*)(X + (size_t)gr * 128))[c4];
            float s = rsqrtf(fmaxf((float)g_outdeg[gr], 1.f));
            v.x *= s; v.y *= s; v.z *= s; v.w *= s;
        }
        *((float4*)(Xs + r * 132 + c4 * 4)) = v;
    }
    __syncthreads();

    constexpr int CG  = COLS / 4;
    constexpr int RGC = 256 / CG;
    constexpr int RPT = 64 / RGC;
    const int cg = tid % CG;
    const int rg = tid / CG;

    float acc[RPT][4];
#pragma unroll
    for (int i = 0; i < RPT; ++i)
#pragma unroll
        for (int j = 0; j < 4; ++j) acc[i][j] = 0.f;

    const float* xbase = Xs + rg * RPT * 132;
    const float4* wc = ((const float4*)Ws) + cg;
#pragma unroll 4
    for (int k = 0; k < 128; ++k) {
        float4 b = wc[k * CG];
#pragma unroll
        for (int i = 0; i < RPT; ++i) {
            float a = xbase[i * 132 + k];
            acc[i][0] = fmaf(a, b.x, acc[i][0]);
            acc[i][1] = fmaf(a, b.y, acc[i][1]);
            acc[i][2] = fmaf(a, b.z, acc[i][2]);
            acc[i][3] = fmaf(a, b.w, acc[i][3]);
        }
    }

#pragma unroll
    for (int i = 0; i < RPT; ++i) {
        int gr = r0 + rg * RPT + i;
        if (gr >= n) continue;
        int c = cg * 4;
#pragma unroll
        for (int j = 0; j < 4; ++j)
            if (c + j < NCOUT) P[(size_t)gr * NCOUT + c + j] = acc[i][j];
    }
}

// ---------------- CSR aggregation over fp16 P, full warp per node ----------------
template<bool RELU>
__global__ void __launch_bounds__(256)
k_csr_agg128_h(const float* __restrict__ b, float* __restrict__ out, int n) {
    int w    = (blockIdx.x * blockDim.x + threadIdx.x) >> 5;
    if (w >= n) return;
    int lane = threadIdx.x & 31;
    int sub  = lane & 15;
    int grp  = lane >> 4;

    int beg = g_rowstart[w];
    int end = g_rowstart[w + 1];

    float acc[8];
#pragma unroll
    for (int j = 0; j < 8; ++j) acc[j] = 0.f;

    const uint4* P16 = (const uint4*)g_P16;

    for (int base = beg; base < end; base += 32) {
        int cnt = min(32, end - base);
        int myidx = (lane < cnt) ? g_esrc[base + lane] : 0;
        int j = 0;
        for (; j + 4 <= cnt; j += 4) {
            int sA = __shfl_sync(0xffffffffu, myidx, j + grp);
            int sB = __shfl_sync(0xffffffffu, myidx, j + 2 + grp);
            uint4 vA = P16[(size_t)sA * 16 + sub];
            uint4 vB = P16[(size_t)sB * 16 + sub];
#pragma unroll
            for (int q = 0; q < 4; ++q) {
                uint32_t uA = (&vA.x)[q];
                uint32_t uB = (&vB.x)[q];
                float2 fA = __half22float2(*(__half2*)&uA);
                float2 fB = __half22float2(*(__half2*)&uB);
                acc[2 * q]     += fA.x + fB.x;
                acc[2 * q + 1] += fA.y + fB.y;
            }
        }
        for (; j + 2 <= cnt; j += 2) {
            int s = __shfl_sync(0xffffffffu, myidx, j + grp);
            uint4 v = P16[(size_t)s * 16 + sub];
#pragma unroll
            for (int q = 0; q < 4; ++q) {
                uint32_t u = (&v.x)[q];
                float2 f = __half22float2(*(__half2*)&u);
                acc[2 * q]     += f.x;
                acc[2 * q + 1] += f.y;
            }
        }
        if (j < cnt) {
            int s = __shfl_sync(0xffffffffu, myidx, j);
            if (grp == 0) {
                uint4 v = P16[(size_t)s * 16 + sub];
#pragma unroll
                for (int q = 0; q < 4; ++q) {
                    uint32_t u = (&v.x)[q];
                    float2 f = __half22float2(*(__half2*)&u);
                    acc[2 * q]     += f.x;
                    acc[2 * q + 1] += f.y;
                }
            }
        }
    }

#pragma unroll
    for (int q = 0; q < 8; ++q)
        acc[q] += __shfl_xor_sync(0xffffffffu, acc[q], 16);

    if (grp == 0) {
        float sc = rsqrtf(fmaxf((float)g_indeg[w], 1.f));
        const float4* b4 = ((const float4*)b) + sub * 2;
        float4 bb0 = b4[0];
        float4 bb1 = b4[1];
        float4 r0, r1;
        r0.x = fmaf(acc[0], sc, bb0.x);
        r0.y = fmaf(acc[1], sc, bb0.y);
        r0.z = fmaf(acc[2], sc, bb0.z);
        r0.w = fmaf(acc[3], sc, bb0.w);
        r1.x = fmaf(acc[4], sc, bb1.x);
        r1.y = fmaf(acc[5], sc, bb1.y);
        r1.z = fmaf(acc[6], sc, bb1.z);
        r1.w = fmaf(acc[7], sc, bb1.w);
        if (RELU) {
            r0.x = fmaxf(r0.x, 0.f); r0.y = fmaxf(r0.y, 0.f);
            r0.z = fmaxf(r0.z, 0.f); r0.w = fmaxf(r0.w, 0.f);
            r1.x = fmaxf(r1.x, 0.f); r1.y = fmaxf(r1.y, 0.f);
            r1.z = fmaxf(r1.z, 0.f); r1.w = fmaxf(r1.w, 0.f);
        }
        float4* orow = ((float4*)(out + (size_t)w * 128)) + sub * 2;
        orow[0] = r0;
        orow[1] = r1;
    }
}

// ---------------- final aggregation over fp32 P (40 dims) ----------------
__global__ void __launch_bounds__(256)
k_agg40(const float* __restrict__ b, float* __restrict__ out, int n) {
    int t = blockIdx.x * blockDim.x + threadIdx.x;
    if (t >= n * 10) return;
    int node = t / 10;
    int g    = t - node * 10;

    int beg = g_rowstart[node];
    int end = g_rowstart[node + 1];

    float4 acc = make_float4(0.f, 0.f, 0.f, 0.f);
    const float4* P4 = (const float4*)g_P;
    int e = beg;
    for (; e + 2 <= end; e += 2) {
        int s0 = g_esrc[e];
        int s1 = g_esrc[e + 1];
        float4 v0 = P4[(size_t)s0 * 10 + g];
        float4 v1 = P4[(size_t)s1 * 10 + g];
        acc.x += v0.x; acc.y += v0.y; acc.z += v0.z; acc.w += v0.w;
        acc.x += v1.x; acc.y += v1.y; acc.z += v1.z; acc.w += v1.w;
    }
    if (e < end) {
        int s = g_esrc[e];
        float4 v = P4[(size_t)s * 10 + g];
        acc.x += v.x; acc.y += v.y; acc.z += v.z; acc.w += v.w;
    }

    float sc = rsqrtf(fmaxf((float)g_indeg[node], 1.f));
    float4 bb = ((const float4*)b)[g];
    float4 r;
    r.x = fmaf(acc.x, sc, bb.x);
    r.y = fmaf(acc.y, sc, bb.y);
    r.z = fmaf(acc.z, sc, bb.z);
    r.w = fmaf(acc.w, sc, bb.w);
    ((float4*)(out + (size_t)node * 40))[g] = r;
}

// ---------------- launch ----------------
extern "C" void kernel_launch(void* const* d_in, const int* in_sizes, int n_in,
                              void* d_out, int out_size) {
    const float* feat = (const float*)d_in[0];
    const float* W1   = (const float*)d_in[1];
    const float* b1   = (const float*)d_in[2];
    const float* W2   = (const float*)d_in[3];
    const float* b2   = (const float*)d_in[4];
    const float* W3   = (const float*)d_in[5];
    const float* b3   = (const float*)d_in[6];
    const int*   src  = (const int*)d_in[7];
    const int*   dst  = (const int*)d_in[8];

    const int N  = in_sizes[0] / 128;
    const int nE = in_sizes[7];
    float* out = (float*)d_out;

    __half* P16 = nullptr;
    float *P = nullptr, *H = nullptr;
    void *odeg = nullptr, *ideg = nullptr;
    cudaGetSymbolAddress((void**)&P16, g_P16);
    cudaGetSymbolAddress((void**)&P, g_P);
    cudaGetSymbolAddress((void**)&H, g_H);
    cudaGetSymbolAddress(&odeg, g_outdeg);
    cudaGetSymbolAddress(&ideg, g_indeg);

    const int SMEM64H = (64 * 132 + 64 * 128) * 4;   // 66560 B -> 3 CTAs/SM
    const int SMEM3   = (128 * 64 + 64 * 132) * 4;   // 66560 B
    cudaFuncSetAttribute(k_gemm64_h, cudaFuncAttributeMaxDynamicSharedMemorySize, SMEM64H);
    cudaFuncSetAttribute(k_gemm<64, 40>, cudaFuncAttributeMaxDynamicSharedMemorySize, SMEM3);

    const int T = 256;
    const int gemmBlocks  = (N + 63) / 64;
    const int aggBlocks   = (N * 32 + T - 1) / T;
    const int eBlocks     = (nE + T - 1) / T;

    cudaStream_t s1;
    cudaStreamCreateWithFlags(&s1, cudaStreamNonBlocking);
    cudaEvent_t e1, e2;
    cudaEventCreateWithFlags(&e1, cudaEventDisableTiming);
    cudaEventCreateWithFlags(&e2, cudaEventDisableTiming);

    // prologue
    cudaMemsetAsync(odeg, 0, (size_t)N * 4, 0);
    cudaMemsetAsync(ideg, 0, (size_t)N * 4, 0);
    k_deg_both<<<eBlocks, T>>>(src, dst, nE);

    // fork: CSR build on s1, GEMM1 on main
    cudaEventRecord(e1, 0);
    cudaStreamWaitEvent(s1, e1, 0);
    k_scan_all<<<1, 1024, 0, s1>>>(N);
    k_scatter<<<eBlocks, T, 0, s1>>>(src, dst, nE);
    cudaEventRecord(e2, s1);

    k_gemm64_h<<<gemmBlocks, T, SMEM64H>>>(feat, W1, P16, N);

    // join
    cudaStreamWaitEvent(0, e2, 0);

    // layer 1 aggregation
    k_csr_agg128_h<true><<<aggBlocks, T>>>(b1, H, N);

    // layer 2
    k_gemm64_h<<<gemmBlocks, T, SMEM64H>>>(H, W2, P16, N);
    k_csr_agg128_h<true><<<aggBlocks, T>>>(b2, H, N);

    // layer 3 (fp32)
    k_gemm<64, 40><<<gemmBlocks, T, SMEM3>>>(H, W3, P, N);
    k_agg40<<<(N * 10 + T - 1) / T, T>>>(b3, out, N);

    cudaStreamCaptureStatus cap = cudaStreamCaptureStatusNone;
    cudaStreamIsCapturing(s1, &cap);
    if (cap == cudaStreamCaptureStatusNone) {
        cudaEventDestroy(e1);
        cudaEventDestroy(e2);
        cudaStreamDestroy(s1);
    }
}

// round 11
// speedup vs baseline: 1.2972x; 1.0288x over previous
#include <cuda_runtime.h>
#include <cuda_fp16.h>
#include <cstdint>

#define NMAX 50000
#define NEMAX 1000000

// ---------------- scratch ----------------
__device__ __align__(16) __half g_P16[(size_t)NMAX * 128];
__device__ __align__(16) float  g_P  [(size_t)NMAX * 40 + 8];
__device__ __align__(16) float  g_H  [(size_t)NMAX * 128];
__device__ __align__(16) int    g_outdeg[NMAX + 8];
__device__ __align__(16) int    g_indeg [NMAX + 8];
__device__ int g_esrc[NEMAX];
__device__ int g_rowstart[NMAX + 8];
__device__ int g_cursor[NMAX + 8];

// ---------------- helpers ----------------
__device__ __forceinline__ uint32_t tf32_bits(float f) {
    uint32_t u;
    asm("cvt.rna.tf32.f32 %0, %1;" : "=r"(u) : "f"(f));
    return u;
}
__device__ __forceinline__ void mma_tf32_k4(
    float& c0, float& c1, float& c2, float& c3,
    uint32_t a0, uint32_t a1, uint32_t b0)
{
    asm volatile(
        "mma.sync.aligned.m16n8k4.row.col.f32.tf32.tf32.f32 "
        "{%0,%1,%2,%3}, {%4,%5}, {%6}, {%0,%1,%2,%3};"
        : "+f"(c0), "+f"(c1), "+f"(c2), "+f"(c3)
        : "r"(a0), "r"(a1), "r"(b0));
}

// ---------------- prologue ----------------
__global__ void k_deg_both(const int* __restrict__ src, const int* __restrict__ dst, int nE) {
    int i = blockIdx.x * blockDim.x + threadIdx.x;
    if (i < nE) {
        atomicAdd(&g_outdeg[src[i]], 1);
        atomicAdd(&g_indeg[dst[i]], 1);
    }
}

__global__ void __launch_bounds__(1024)
k_scan_all(int n) {
    __shared__ int part[1024];
    int tid = threadIdx.x;
    int chunk = (n + 1023) >> 10;
    int s = tid * chunk;
    int e = min(s + chunk, n);
    int sum = 0;
    for (int i = s; i < e; ++i) sum += g_indeg[i];
    part[tid] = sum;
    __syncthreads();
    for (int off = 1; off < 1024; off <<= 1) {
        int t = 0;
        if (tid >= off) t = part[tid - off];
        __syncthreads();
        if (tid >= off) part[tid] += t;
        __syncthreads();
    }
    int run = part[tid] - sum;
    for (int i = s; i < e; ++i) {
        int d = g_indeg[i];
        g_rowstart[i] = run;
        g_cursor[i]   = run;
        run += d;
    }
    if (tid == 1023) g_rowstart[n] = run;
}

__global__ void k_scatter(const int* __restrict__ src, const int* __restrict__ dst, int nE) {
    int i = blockIdx.x * blockDim.x + threadIdx.x;
    if (i < nE) {
        int d = dst[i];
        int pos = atomicAdd(&g_cursor[d], 1);
        g_esrc[pos] = src[i];
    }
}

// ---------------- tf32 tensor-core GEMM: P16[r,:] = tf32(X[r,:]*onorm) @ tf32(W) --
// Tile 128 rows x 128 cols, 256 threads (8 warps), warp = 16 rows.
// Xs: [128][132] tf32 words. Wt: [128 n][68] tf32 words, one K-half at a time.
__global__ void __launch_bounds__(256)
k_gemm_tf32(const float* __restrict__ X, const float* __restrict__ W,
            __half* __restrict__ P, int n) {
    extern __shared__ uint32_t smu[];
    const int XS = 128 * 132;              // word offset of Wt

    const int tid  = threadIdx.x;
    const int lane = tid & 31;
    const int w    = tid >> 5;
    const int r0   = blockIdx.x * 128;
    const int qr   = lane >> 2;            // quad row 0..7
    const int qc   = lane & 3;             // quad col 0..3

    // stage Xs (tf32 bits, onorm fused)
    for (int q = tid; q < 128 * 32; q += 256) {
        int r = q >> 5, c4 = q & 31;
        int gr = r0 + r;
        float4 v = make_float4(0.f, 0.f, 0.f, 0.f);
        if (gr < n) {
            v = ((const float4*)(X + (size_t)gr * 128))[c4];
            float s = rsqrtf(fmaxf((float)g_outdeg[gr], 1.f));
            v.x *= s; v.y *= s; v.z *= s; v.w *= s;
        }
        uint32_t* p = smu + r * 132 + c4 * 4;
        p[0] = tf32_bits(v.x);
        p[1] = tf32_bits(v.y);
        p[2] = tf32_bits(v.z);
        p[3] = tf32_bits(v.w);
    }

    float acc[16][4];
#pragma unroll
    for (int t = 0; t < 16; ++t)
#pragma unroll
        for (int j = 0; j < 4; ++j) acc[t][j] = 0.f;

    const uint32_t* xrow = smu + (16 * w + qr) * 132 + qc;
    const uint32_t* brow = smu + XS + qr * 68 + qc;

    for (int half = 0; half < 2; ++half) {
        __syncthreads();
        // stage Wt[n][kk] = tf32(W[(64*half+kk)*128 + n]); coalesced gmem read over n
        for (int q = tid; q < 64 * 128; q += 256) {
            int kk = q >> 7, nn = q & 127;
            smu[XS + nn * 68 + kk] = tf32_bits(W[(half * 64 + kk) * 128 + nn]);
        }
        __syncthreads();

        const uint32_t* xh = xrow + half * 64;
#pragma unroll
        for (int kt = 0; kt < 16; ++kt) {
            uint32_t a0 = xh[kt * 4];
            uint32_t a1 = xh[8 * 132 + kt * 4];
            uint32_t b[16];
#pragma unroll
            for (int nt = 0; nt < 16; ++nt)
                b[nt] = brow[nt * 8 * 68 + kt * 4];
#pragma unroll
            for (int nt = 0; nt < 16; ++nt)
                mma_tf32_k4(acc[nt][0], acc[nt][1], acc[nt][2], acc[nt][3],
                            a0, a1, b[nt]);
        }
    }

    // epilogue: c0,c1 -> row qr, cols 8nt+2qc,+1 ; c2,c3 -> row qr+8
    {
        int r1 = r0 + 16 * w + qr;
        int r2 = r1 + 8;
        __half* prow1 = P + (size_t)r1 * 128;
        __half* prow2 = P + (size_t)r2 * 128;
        bool ok1 = (r1 < n), ok2 = (r2 < n);
#pragma unroll
        for (int nt = 0; nt < 16; ++nt) {
            int col = nt * 8 + 2 * qc;
            if (ok1) {
                __half2 h = __floats2half2_rn(acc[nt][0], acc[nt][1]);
                *(__half2*)(prow1 + col) = h;
            }
            if (ok2) {
                __half2 h = __floats2half2_rn(acc[nt][2], acc[nt][3]);
                *(__half2*)(prow2 + col) = h;
            }
        }
    }
}

// ---------------- GEMM layer 3 (128 -> 40), fp32 FFMA ----------------
template<int COLS, int NCOUT>
__global__ void __launch_bounds__(256)
k_gemm(const float* __restrict__ X, const float* __restrict__ W,
       float* __restrict__ P, int n) {
    extern __shared__ float sm[];
    float* Ws = sm;
    float* Xs = sm + 128 * COLS;

    const int tid = threadIdx.x;
    const int r0  = blockIdx.x * 64;

    for (int q = tid; q < 128 * COLS; q += 256) {
        int k = q / COLS, c = q % COLS;
        Ws[q] = (c < NCOUT) ? W[k * NCOUT + c] : 0.f;
    }
    for (int q = tid; q < 64 * 32; q += 256) {
        int r = q >> 5, c4 = q & 31;
        int gr = r0 + r;
        float4 v = make_float4(0.f, 0.f, 0.f, 0.f);
        if (gr < n) {
            v = ((const float4*)(X + (size_t)gr * 128))[c4];
            float s = rsqrtf(fmaxf((float)g_outdeg[gr], 1.f));
            v.x *= s; v.y *= s; v.z *= s; v.w *= s;
        }
        *((float4*)(Xs + r * 132 + c4 * 4)) = v;
    }
    __syncthreads();

    constexpr int CG  = COLS / 4;
    constexpr int RGC = 256 / CG;
    constexpr int RPT = 64 / RGC;
    const int cg = tid % CG;
    const int rg = tid / CG;

    float acc[RPT][4];
#pragma unroll
    for (int i = 0; i < RPT; ++i)
#pragma unroll
        for (int j = 0; j < 4; ++j) acc[i][j] = 0.f;

    const float* xbase = Xs + rg * RPT * 132;
    const float4* wc = ((const float4*)Ws) + cg;
#pragma unroll 4
    for (int k = 0; k < 128; ++k) {
        float4 b = wc[k * CG];
#pragma unroll
        for (int i = 0; i < RPT; ++i) {
            float a = xbase[i * 132 + k];
            acc[i][0] = fmaf(a, b.x, acc[i][0]);
            acc[i][1] = fmaf(a, b.y, acc[i][1]);
            acc[i][2] = fmaf(a, b.z, acc[i][2]);
            acc[i][3] = fmaf(a, b.w, acc[i][3]);
        }
    }

#pragma unroll
    for (int i = 0; i < RPT; ++i) {
        int gr = r0 + rg * RPT + i;
        if (gr >= n) continue;
        int c = cg * 4;
#pragma unroll
        for (int j = 0; j < 4; ++j)
            if (c + j < NCOUT) P[(size_t)gr * NCOUT + c + j] = acc[i][j];
    }
}

// ---------------- CSR aggregation over fp16 P, full warp per node ----------------
template<bool RELU>
__global__ void __launch_bounds__(256)
k_csr_agg128_h(const float* __restrict__ b, float* __restrict__ out, int n) {
    int w    = (blockIdx.x * blockDim.x + threadIdx.x) >> 5;
    if (w >= n) return;
    int lane = threadIdx.x & 31;
    int sub  = lane & 15;
    int grp  = lane >> 4;

    int beg = g_rowstart[w];
    int end = g_rowstart[w + 1];

    float acc[8];
#pragma unroll
    for (int j = 0; j < 8; ++j) acc[j] = 0.f;

    const uint4* P16 = (const uint4*)g_P16;

    for (int base = beg; base < end; base += 32) {
        int cnt = min(32, end - base);
        int myidx = (lane < cnt) ? g_esrc[base + lane] : 0;
        int j = 0;
        for (; j + 4 <= cnt; j += 4) {
            int sA = __shfl_sync(0xffffffffu, myidx, j + grp);
            int sB = __shfl_sync(0xffffffffu, myidx, j + 2 + grp);
            uint4 vA = P16[(size_t)sA * 16 + sub];
            uint4 vB = P16[(size_t)sB * 16 + sub];
#pragma unroll
            for (int q = 0; q < 4; ++q) {
                uint32_t uA = (&vA.x)[q];
                uint32_t uB = (&vB.x)[q];
                float2 fA = __half22float2(*(__half2*)&uA);
                float2 fB = __half22float2(*(__half2*)&uB);
                acc[2 * q]     += fA.x + fB.x;
                acc[2 * q + 1] += fA.y + fB.y;
            }
        }
        for (; j + 2 <= cnt; j += 2) {
            int s = __shfl_sync(0xffffffffu, myidx, j + grp);
            uint4 v = P16[(size_t)s * 16 + sub];
#pragma unroll
            for (int q = 0; q < 4; ++q) {
                uint32_t u = (&v.x)[q];
                float2 f = __half22float2(*(__half2*)&u);
                acc[2 * q]     += f.x;
                acc[2 * q + 1] += f.y;
            }
        }
        if (j < cnt) {
            int s = __shfl_sync(0xffffffffu, myidx, j);
            if (grp == 0) {
                uint4 v = P16[(size_t)s * 16 + sub];
#pragma unroll
                for (int q = 0; q < 4; ++q) {
                    uint32_t u = (&v.x)[q];
                    float2 f = __half22float2(*(__half2*)&u);
                    acc[2 * q]     += f.x;
                    acc[2 * q + 1] += f.y;
                }
            }
        }
    }

#pragma unroll
    for (int q = 0; q < 8; ++q)
        acc[q] += __shfl_xor_sync(0xffffffffu, acc[q], 16);

    if (grp == 0) {
        float sc = rsqrtf(fmaxf((float)g_indeg[w], 1.f));
        const float4* b4 = ((const float4*)b) + sub * 2;
        float4 bb0 = b4[0];
        float4 bb1 = b4[1];
        float4 r0, r1;
        r0.x = fmaf(acc[0], sc, bb0.x);
        r0.y = fmaf(acc[1], sc, bb0.y);
        r0.z = fmaf(acc[2], sc, bb0.z);
        r0.w = fmaf(acc[3], sc, bb0.w);
        r1.x = fmaf(acc[4], sc, bb1.x);
        r1.y = fmaf(acc[5], sc, bb1.y);
        r1.z = fmaf(acc[6], sc, bb1.z);
        r1.w = fmaf(acc[7], sc, bb1.w);
        if (RELU) {
            r0.x = fmaxf(r0.x, 0.f); r0.y = fmaxf(r0.y, 0.f);
            r0.z = fmaxf(r0.z, 0.f); r0.w = fmaxf(r0.w, 0.f);
            r1.x = fmaxf(r1.x, 0.f); r1.y = fmaxf(r1.y, 0.f);
            r1.z = fmaxf(r1.z, 0.f); r1.w = fmaxf(r1.w, 0.f);
        }
        float4* orow = ((float4*)(out + (size_t)w * 128)) + sub * 2;
        orow[0] = r0;
        orow[1] = r1;
    }
}

// ---------------- final aggregation over fp32 P (40 dims) ----------------
__global__ void __launch_bounds__(256)
k_agg40(const float* __restrict__ b, float* __restrict__ out, int n) {
    int t = blockIdx.x * blockDim.x + threadIdx.x;
    if (t >= n * 10) return;
    int node = t / 10;
    int g    = t - node * 10;

    int beg = g_rowstart[node];
    int end = g_rowstart[node + 1];

    float4 acc = make_float4(0.f, 0.f, 0.f, 0.f);
    const float4* P4 = (const float4*)g_P;
    int e = beg;
    for (; e + 2 <= end; e += 2) {
        int s0 = g_esrc[e];
        int s1 = g_esrc[e + 1];
        float4 v0 = P4[(size_t)s0 * 10 + g];
        float4 v1 = P4[(size_t)s1 * 10 + g];
        acc.x += v0.x; acc.y += v0.y; acc.z += v0.z; acc.w += v0.w;
        acc.x += v1.x; acc.y += v1.y; acc.z += v1.z; acc.w += v1.w;
    }
    if (e < end) {
        int s = g_esrc[e];
        float4 v = P4[(size_t)s * 10 + g];
        acc.x += v.x; acc.y += v.y; acc.z += v.z; acc.w += v.w;
    }

    float sc = rsqrtf(fmaxf((float)g_indeg[node], 1.f));
    float4 bb = ((const float4*)b)[g];
    float4 r;
    r.x = fmaf(acc.x, sc, bb.x);
    r.y = fmaf(acc.y, sc, bb.y);
    r.z = fmaf(acc.z, sc, bb.z);
    r.w = fmaf(acc.w, sc, bb.w);
    ((float4*)(out + (size_t)node * 40))[g] = r;
}

// ---------------- launch ----------------
extern "C" void kernel_launch(void* const* d_in, const int* in_sizes, int n_in,
                              void* d_out, int out_size) {
    const float* feat = (const float*)d_in[0];
    const float* W1   = (const float*)d_in[1];
    const float* b1   = (const float*)d_in[2];
    const float* W2   = (const float*)d_in[3];
    const float* b2   = (const float*)d_in[4];
    const float* W3   = (const float*)d_in[5];
    const float* b3   = (const float*)d_in[6];
    const int*   src  = (const int*)d_in[7];
    const int*   dst  = (const int*)d_in[8];

    const int N  = in_sizes[0] / 128;
    const int nE = in_sizes[7];
    float* out = (float*)d_out;

    __half* P16 = nullptr;
    float *P = nullptr, *H = nullptr;
    void *odeg = nullptr, *ideg = nullptr;
    cudaGetSymbolAddress((void**)&P16, g_P16);
    cudaGetSymbolAddress((void**)&P, g_P);
    cudaGetSymbolAddress((void**)&H, g_H);
    cudaGetSymbolAddress(&odeg, g_outdeg);
    cudaGetSymbolAddress(&ideg, g_indeg);

    const int SMEM_TF = (128 * 132 + 128 * 68) * 4;   // 102400 B -> 2 CTAs/SM
    const int SMEM3   = (128 * 64 + 64 * 132) * 4;    // 66560 B
    cudaFuncSetAttribute(k_gemm_tf32, cudaFuncAttributeMaxDynamicSharedMemorySize, SMEM_TF);
    cudaFuncSetAttribute(k_gemm<64, 40>, cudaFuncAttributeMaxDynamicSharedMemorySize, SMEM3);

    const int T = 256;
    const int gemmBlocks  = (N + 127) / 128;
    const int gemm3Blocks = (N + 63) / 64;
    const int aggBlocks   = (N * 32 + T - 1) / T;
    const int eBlocks     = (nE + T - 1) / T;

    cudaStream_t s1;
    cudaStreamCreateWithFlags(&s1, cudaStreamNonBlocking);
    cudaEvent_t e1, e2;
    cudaEventCreateWithFlags(&e1, cudaEventDisableTiming);
    cudaEventCreateWithFlags(&e2, cudaEventDisableTiming);

    // prologue
    cudaMemsetAsync(odeg, 0, (size_t)N * 4, 0);
    cudaMemsetAsync(ideg, 0, (size_t)N * 4, 0);
    k_deg_both<<<eBlocks, T>>>(src, dst, nE);

    // fork: CSR build on s1, GEMM1 on main
    cudaEventRecord(e1, 0);
    cudaStreamWaitEvent(s1, e1, 0);
    k_scan_all<<<1, 1024, 0, s1>>>(N);
    k_scatter<<<eBlocks, T, 0, s1>>>(src, dst, nE);
    cudaEventRecord(e2, s1);

    k_gemm_tf32<<<gemmBlocks, T, SMEM_TF>>>(feat, W1, P16, N);

    // join
    cudaStreamWaitEvent(0, e2, 0);

    // layer 1 aggregation
    k_csr_agg128_h<true><<<aggBlocks, T>>>(b1, H, N);

    // layer 2
    k_gemm_tf32<<<gemmBlocks, T, SMEM_TF>>>(H, W2, P16, N);
    k_csr_agg128_h<true><<<aggBlocks, T>>>(b2, H, N);

    // layer 3 (fp32)
    k_gemm<64, 40><<<gemm3Blocks, T, SMEM3>>>(H, W3, P, N);
    k_agg40<<<(N * 10 + T - 1) / T, T>>>(b3, out, N);

    cudaStreamCaptureStatus cap = cudaStreamCaptureStatusNone;
    cudaStreamIsCapturing(s1, &cap);
    if (cap == cudaStreamCaptureStatusNone) {
        cudaEventDestroy(e1);
        cudaEventDestroy(e2);
        cudaStreamDestroy(s1);
    }
}